// round 15
// baseline (speedup 1.0000x reference)
#include <cuda_runtime.h>
#include <cuda_fp16.h>
#include <math_constants.h>
#include <cstdint>

#define DMODEL 1024
#define NHEADS 16
#define DHEAD  64
#define NBATCH 2
#define SQ     2048
#define SK     2048
#define MROWS  (NBATCH * SQ)   // 4096

// Q pre-scale: 1/sqrt(64) * log2(e)  (flash uses exp2)
#define QSCALE 0.18033688011112042f

// ---------------------------------------------------------------------------
// Scratch (device globals: no allocation allowed)
// ---------------------------------------------------------------------------
__device__ __half g_qh[(size_t)NBATCH * NHEADS * SQ * DHEAD];   // [b,h,q,d], pre-scaled
__device__ __half g_kh[(size_t)NBATCH * NHEADS * SK * DHEAD];   // [b,h,s,d]
__device__ __half g_vt[(size_t)NBATCH * NHEADS * DHEAD * SK];   // [b,h,d,s]  TRANSPOSED
__device__ __half g_attn[(size_t)NBATCH * SQ * DMODEL];          // [b,q,h*64+d]
__device__ __half g_act[(size_t)3 * MROWS * DMODEL];             // fp16(q,k,v)
__device__ __half g_w[(size_t)3 * DMODEL * DMODEL];              // fp16(Wq,Wk,Wv)  [k][n]
__device__ __half g_wo[(size_t)DMODEL * DMODEL];                 // fp16(Wo)        [k][n]

// ---------------------------------------------------------------------------
// helpers
// ---------------------------------------------------------------------------
__device__ __forceinline__ void cp_async16(void* smem, const void* gmem) {
    uint32_t s = (uint32_t)__cvta_generic_to_shared(smem);
    asm volatile("cp.async.cg.shared.global [%0], [%1], 16;\n" :: "r"(s), "l"(gmem));
}
__device__ __forceinline__ void cp_commit() { asm volatile("cp.async.commit_group;\n"); }
template<int N> __device__ __forceinline__ void cp_wait() {
    asm volatile("cp.async.wait_group %0;\n" :: "n"(N));
}
__device__ __forceinline__ uint32_t pack_f16x2(float hi, float lo) {
    uint32_t r; asm("cvt.rn.f16x2.f32 %0, %1, %2;" : "=r"(r) : "f"(hi), "f"(lo)); return r;
}
__device__ __forceinline__ uint32_t h2exp2(uint32_t x) {
    uint32_t r; asm("ex2.approx.f16x2 %0, %1;" : "=r"(r) : "r"(x)); return r;
}
__device__ __forceinline__ void mma_f16(float c[4], const uint32_t a[4], uint32_t b0, uint32_t b1) {
    asm volatile("mma.sync.aligned.m16n8k16.row.col.f32.f16.f16.f32 "
        "{%0,%1,%2,%3}, {%4,%5,%6,%7}, {%8,%9}, {%0,%1,%2,%3};\n"
        : "+f"(c[0]), "+f"(c[1]), "+f"(c[2]), "+f"(c[3])
        : "r"(a[0]), "r"(a[1]), "r"(a[2]), "r"(a[3]), "r"(b0), "r"(b1));
}
__device__ __forceinline__ void ldsm_x4(uint32_t& r0, uint32_t& r1,
                                        uint32_t& r2, uint32_t& r3, uint32_t addr) {
    asm volatile("ldmatrix.sync.aligned.m8n8.x4.shared.b16 {%0,%1,%2,%3}, [%4];"
        : "=r"(r0), "=r"(r1), "=r"(r2), "=r"(r3) : "r"(addr));
}
__device__ __forceinline__ void ldsm_x4_trans(uint32_t& r0, uint32_t& r1,
                                              uint32_t& r2, uint32_t& r3, uint32_t addr) {
    asm volatile("ldmatrix.sync.aligned.m8n8.x4.trans.shared.b16 {%0,%1,%2,%3}, [%4];"
        : "=r"(r0), "=r"(r1), "=r"(r2), "=r"(r3) : "r"(addr));
}
__device__ __forceinline__ uint32_t smem_u32(const void* p) {
    return (uint32_t)__cvta_generic_to_shared(p);
}

// ---------------------------------------------------------------------------
// Preconvert: inputs + weights -> fp16. grid (4096, 7) x 256.
// ---------------------------------------------------------------------------
__global__ __launch_bounds__(256)
void preconvert_kernel(const float4* __restrict__ q, const float4* __restrict__ k,
                       const float4* __restrict__ v, const float4* __restrict__ wq,
                       const float4* __restrict__ wk, const float4* __restrict__ wv,
                       const float4* __restrict__ wo)
{
    const int y = blockIdx.y;
    const float4* src;
    __half* dst;
    int n4;
    if (y < 3) {
        src = (y == 0) ? q : (y == 1) ? k : v;
        dst = g_act + (size_t)y * (MROWS * DMODEL);
        n4 = MROWS * DMODEL / 4;
    } else {
        src = (y == 3) ? wq : (y == 4) ? wk : (y == 5) ? wv : wo;
        dst = (y < 6) ? g_w + (size_t)(y - 3) * (DMODEL * DMODEL) : g_wo;
        n4 = DMODEL * DMODEL / 4;
    }
    int idx = blockIdx.x * 256 + threadIdx.x;
    if (idx < n4) {
        float4 s = src[idx];
        uint2 u;
        u.x = pack_f16x2(s.y, s.x);
        u.y = pack_f16x2(s.w, s.z);
        *(uint2*)(dst + 4 * (size_t)idx) = u;
    }
}

// ---------------------------------------------------------------------------
// FP16 GEMM (manual mma + ldmatrix, R13/R14 inner loop). CTA 128x128, 8 warps
// (warp tile 32x64), BK=32, triple-buffered cp.async, fp32 accum,
// direct-to-global epilogue.
// SINGLE-WAVE: MODE 0 runs all three projections (z=0,1,2) in ONE 256-CTA
// grid (each CTA loops z), eliminating the 2.59-wave tail of the old 768-CTA
// launch. MODE 1 (O-proj) loops once.
// ---------------------------------------------------------------------------
#define G_ALD 40     // halves per A row (32 + 8 pad)
#define G_BLD 136    // halves per B row (128 + 8 pad)
#define G_ASZ (128 * G_ALD)
#define G_BSZ (32 * G_BLD)
#define GEMM_SMEM (3 * (G_ASZ + G_BSZ) * (int)sizeof(__half))  // 56832

template<int MODE>
__global__ __launch_bounds__(256, 2)
void gemm_f16_kernel(const float* __restrict__ bias0,
                     const float* __restrict__ bias1,
                     const float* __restrict__ bias2,
                     float* __restrict__ out)
{
    extern __shared__ __half gsm[];
    __half* Asm = gsm;                  // [3][128][40]
    __half* Bsm = gsm + 3 * G_ASZ;      // [3][32][136]

    const int tid    = threadIdx.x;
    const int wid    = tid >> 5;
    const int lane   = tid & 31;
    const int warp_m = wid >> 1;     // 0..3 (32 rows each)
    const int warp_n = wid & 1;      // 0..1 (64 cols each)
    const int m0 = blockIdx.y * 128;
    const int n0 = blockIdx.x * 128;

    const uint32_t a_lane = (uint32_t)((warp_m * 32 + (lane & 15)) * G_ALD + (lane >> 4) * 8) * 2;
    const uint32_t b_lane = (uint32_t)((((lane >> 3) & 1) * 8 + (lane & 7)) * G_BLD
                                       + warp_n * 64 + (lane >> 4) * 8) * 2;
    const int g  = lane >> 2;
    const int qq = lane & 3;

    const int NZ = (MODE == 0) ? 3 : 1;
    for (int z = 0; z < NZ; z++) {
        const __half* Ap   = (MODE == 1) ? g_attn : g_act + (size_t)z * (MROWS * DMODEL);
        const __half* W    = (MODE == 1) ? g_wo   : g_w   + (size_t)z * (DMODEL * DMODEL);
        const float* bias  = (MODE == 1) ? bias0  : (z == 0) ? bias0 : (z == 1) ? bias1 : bias2;

        float acc[2][8][4];
#pragma unroll
        for (int i = 0; i < 2; i++)
#pragma unroll
            for (int j = 0; j < 8; j++)
#pragma unroll
                for (int t = 0; t < 4; t++) acc[i][j][t] = 0.0f;

#define GEMM_PREFETCH(IT, BUF)                                                      \
    {                                                                               \
        int k0 = (IT) * 32;                                                         \
        _Pragma("unroll")                                                           \
        for (int i = 0; i < 2; i++) {                                               \
            int idx = tid + i * 256;                                                \
            int r = idx >> 2, c = idx & 3;                                          \
            cp_async16(&Asm[(BUF) * G_ASZ + r * G_ALD + c * 8],                     \
                       Ap + (size_t)(m0 + r) * DMODEL + k0 + c * 8);                \
        }                                                                           \
        _Pragma("unroll")                                                           \
        for (int i = 0; i < 2; i++) {                                               \
            int idx = tid + i * 256;                                                \
            int r = idx >> 4, c = idx & 15;                                         \
            cp_async16(&Bsm[(BUF) * G_BSZ + r * G_BLD + c * 8],                     \
                       W + (size_t)(k0 + r) * DMODEL + n0 + c * 8);                 \
        }                                                                           \
        cp_commit();                                                                \
    }

        GEMM_PREFETCH(0, 0);
        GEMM_PREFETCH(1, 1);

        int buf = 0;
        for (int it = 0; it < 32; it++) {
            if (it + 1 < 32) cp_wait<1>(); else cp_wait<0>();
            __syncthreads();
            if (it + 2 < 32) {
                int nbuf = (buf + 2 >= 3) ? buf - 1 : buf + 2;
                GEMM_PREFETCH(it + 2, nbuf);
            }

            const uint32_t abase = smem_u32(Asm + buf * G_ASZ) + a_lane;
            const uint32_t bbase = smem_u32(Bsm + buf * G_BSZ) + b_lane;

#pragma unroll
            for (int kc = 0; kc < 2; kc++) {
                uint32_t a[2][4];
                ldsm_x4(a[0][0], a[0][1], a[0][2], a[0][3], abase + kc * 32);
                ldsm_x4(a[1][0], a[1][1], a[1][2], a[1][3], abase + kc * 32 + 16 * G_ALD * 2);
#pragma unroll
                for (int ni2 = 0; ni2 < 4; ni2++) {
                    uint32_t b0, b1, b2, b3;
                    ldsm_x4_trans(b0, b1, b2, b3, bbase + kc * (16 * G_BLD * 2) + ni2 * 32);
                    mma_f16(acc[0][2 * ni2],     a[0], b0, b1);
                    mma_f16(acc[1][2 * ni2],     a[1], b0, b1);
                    mma_f16(acc[0][2 * ni2 + 1], a[0], b2, b3);
                    mma_f16(acc[1][2 * ni2 + 1], a[1], b2, b3);
                }
            }
            buf = (buf + 1 >= 3) ? 0 : buf + 1;
        }
#undef GEMM_PREFETCH
        // Fence: some warps may still be reading smem from the last iteration
        // when the next z-phase's prefetch would overwrite it.
        __syncthreads();

        // ---- direct epilogue (c0/c1 pairs -> contiguous cols) ----
#pragma unroll
        for (int mi = 0; mi < 2; mi++) {
            const int r0 = m0 + warp_m * 32 + mi * 16 + g;
#pragma unroll
            for (int ni = 0; ni < 8; ni++) {
                const int col = n0 + warp_n * 64 + ni * 8 + 2 * qq;
                const float bv0 = bias[col], bv1 = bias[col + 1];
                float v0 = acc[mi][ni][0] + bv0, v1 = acc[mi][ni][1] + bv1;
                float v2 = acc[mi][ni][2] + bv0, v3 = acc[mi][ni][3] + bv1;
#pragma unroll
                for (int half = 0; half < 2; half++) {
                    const int grow = r0 + half * 8;
                    const float w0 = half ? v2 : v0;
                    const float w1 = half ? v3 : v1;
                    if (MODE == 0) {
                        int b_ = grow >> 11, qr = grow & 2047;
                        int h_ = col >> 6, d_ = col & 63;
                        if (z == 0) {
                            size_t a = (((size_t)(b_ * NHEADS + h_) * SQ) + qr) * DHEAD + d_;
                            *(uint32_t*)(g_qh + a) = pack_f16x2(w1 * QSCALE, w0 * QSCALE);
                        } else if (z == 1) {
                            size_t a = (((size_t)(b_ * NHEADS + h_) * SK) + qr) * DHEAD + d_;
                            *(uint32_t*)(g_kh + a) = pack_f16x2(w1, w0);
                        } else {
                            size_t a = (((size_t)(b_ * NHEADS + h_) * DHEAD) + d_) * SK + qr;
                            g_vt[a] = __float2half(w0);
                            g_vt[a + SK] = __float2half(w1);
                        }
                    } else {
                        *(float2*)(out + (size_t)grow * DMODEL + col) = make_float2(w0, w1);
                    }
                }
            }
        }
    }
}

// ---------------------------------------------------------------------------
// Flash attention fp16 (R14 numerics): register-resident S/O, mma.m16n8k16,
// triple-buffered K/Vt tiles, f16x2 softmax exponentials.
// SINGLE-WAVE: grid (16,16) = 256 CTAs (<= 296 resident slots at 2 CTAs/SM);
// each CTA processes BOTH batches sequentially, eliminating the 1.73-wave tail
// of the old 512-CTA launch.
// ---------------------------------------------------------------------------
#define FLD 72                       // halves per row (64 + 8 pad)
#define FL_TSZ (64 * FLD)            // halves per tile
#define FLASH_SMEM ((6 * FL_TSZ) * (int)sizeof(__half))   // 55296

__global__ __launch_bounds__(256)
void flash_attn_kernel()
{
    extern __shared__ __half fsm[];
    __half* Ksm = fsm;                 // [3][64][FLD]; bufs 0-1 double as Q staging
    __half* Vsm = fsm + 3 * FL_TSZ;    // [3][64][FLD]

    const int q0  = blockIdx.x * 128;
    const int h   = blockIdx.y;
    const int tid = threadIdx.x;
    const int wid = tid >> 5;
    const int lane = tid & 31;
    const int g = lane >> 2;
    const int q = lane & 3;

    for (int b = 0; b < NBATCH; b++) {
        const __half* Qg = g_qh + (((size_t)(b * NHEADS + h) * SQ) + q0) * DHEAD;
        const __half* Kg = g_kh + ((size_t)(b * NHEADS + h) * SK) * DHEAD;
        const __half* Vg = g_vt + ((size_t)(b * NHEADS + h) * DHEAD) * SK;

        // Fence: previous batch's tail MMAs may still read Ksm/Vsm.
        __syncthreads();

        // ---- Stage Q tile (128 x 64 halves) into Ksm bufs 0-1 ----
#pragma unroll
        for (int i = 0; i < 4; i++) {
            int idx = tid + i * 256;
            int r = idx >> 3, c = idx & 7;
            cp_async16(&Ksm[r * FLD + c * 8], Qg + (size_t)r * DHEAD + c * 8);
        }
        cp_commit();
        cp_wait<0>();
        __syncthreads();

        uint32_t qa[4][4];
        {
            const uint32_t* Qw = (const uint32_t*)Ksm;
            const int r0 = wid * 16 + g;
#pragma unroll
            for (int kc = 0; kc < 4; kc++) {
                qa[kc][0] = Qw[(r0)     * (FLD / 2) + kc * 8 + q];
                qa[kc][1] = Qw[(r0 + 8) * (FLD / 2) + kc * 8 + q];
                qa[kc][2] = Qw[(r0)     * (FLD / 2) + kc * 8 + q + 4];
                qa[kc][3] = Qw[(r0 + 8) * (FLD / 2) + kc * 8 + q + 4];
            }
        }
        __syncthreads();   // everyone done reading Q before K overwrites

#define FL_PREFETCH(J, BUF)                                                         \
    {                                                                               \
        _Pragma("unroll")                                                           \
        for (int i = 0; i < 2; i++) {                                               \
            int idx = tid + i * 256;                                                \
            int r = idx >> 3, c = idx & 7;                                          \
            cp_async16(&Ksm[(BUF) * FL_TSZ + r * FLD + c * 8],                      \
                       Kg + (size_t)((J) * 64 + r) * DHEAD + c * 8);                \
            cp_async16(&Vsm[(BUF) * FL_TSZ + r * FLD + c * 8],                      \
                       Vg + (size_t)r * SK + (J) * 64 + c * 8);                     \
        }                                                                           \
        cp_commit();                                                                \
    }

        FL_PREFETCH(0, 0);
        FL_PREFETCH(1, 1);

        float oacc[8][4];
#pragma unroll
        for (int nb = 0; nb < 8; nb++)
#pragma unroll
            for (int t = 0; t < 4; t++) oacc[nb][t] = 0.0f;

        float m0r = -CUDART_INF_F, m1r = -CUDART_INF_F;
        float l0r = 0.0f, l1r = 0.0f;

        const int NT = SK / 64;  // 32
        int buf = 0;
        for (int j = 0; j < NT; j++) {
            if (j + 1 < NT) cp_wait<1>(); else cp_wait<0>();
            __syncthreads();
            if (j + 2 < NT) {
                int nbuf = (buf + 2 >= 3) ? buf - 1 : buf + 2;
                FL_PREFETCH(j + 2, nbuf);
            }

            const uint32_t* Kb = (const uint32_t*)(Ksm + buf * FL_TSZ);
            const uint32_t* Vb = (const uint32_t*)(Vsm + buf * FL_TSZ);

            // ---- S (log2-domain logits; Q pre-scaled) ----
            float sacc[8][4];
#pragma unroll
            for (int nb = 0; nb < 8; nb++) {
#pragma unroll
                for (int t = 0; t < 4; t++) sacc[nb][t] = 0.0f;
#pragma unroll
                for (int kc = 0; kc < 4; kc++) {
                    uint32_t b0 = Kb[(nb * 8 + g) * (FLD / 2) + kc * 8 + q];
                    uint32_t b1 = Kb[(nb * 8 + g) * (FLD / 2) + kc * 8 + q + 4];
                    mma_f16(sacc[nb], qa[kc], b0, b1);
                }
            }

            // ---- online softmax: row maxima (fp32), P = f16x2 exp2 ----
            float mx0 = -CUDART_INF_F, mx1 = -CUDART_INF_F;
#pragma unroll
            for (int nb = 0; nb < 8; nb++) {
                mx0 = fmaxf(mx0, fmaxf(sacc[nb][0], sacc[nb][1]));
                mx1 = fmaxf(mx1, fmaxf(sacc[nb][2], sacc[nb][3]));
            }
            mx0 = fmaxf(mx0, __shfl_xor_sync(0xffffffffu, mx0, 1));
            mx0 = fmaxf(mx0, __shfl_xor_sync(0xffffffffu, mx0, 2));
            mx1 = fmaxf(mx1, __shfl_xor_sync(0xffffffffu, mx1, 1));
            mx1 = fmaxf(mx1, __shfl_xor_sync(0xffffffffu, mx1, 2));

            float mn0 = fmaxf(m0r, mx0), mn1 = fmaxf(m1r, mx1);
            float al0 = exp2f(m0r - mn0), al1 = exp2f(m1r - mn1);
            m0r = mn0; m1r = mn1;

            uint32_t pa[4][4];
            __half2 hs0 = __float2half2_rn(0.0f), hs1 = __float2half2_rn(0.0f);
#pragma unroll
            for (int kc = 0; kc < 4; kc++) {
                pa[kc][0] = h2exp2(pack_f16x2(sacc[2 * kc][1] - mn0,     sacc[2 * kc][0] - mn0));
                pa[kc][1] = h2exp2(pack_f16x2(sacc[2 * kc][3] - mn1,     sacc[2 * kc][2] - mn1));
                pa[kc][2] = h2exp2(pack_f16x2(sacc[2 * kc + 1][1] - mn0, sacc[2 * kc + 1][0] - mn0));
                pa[kc][3] = h2exp2(pack_f16x2(sacc[2 * kc + 1][3] - mn1, sacc[2 * kc + 1][2] - mn1));
                hs0 = __hadd2(hs0, __hadd2(*(__half2*)&pa[kc][0], *(__half2*)&pa[kc][2]));
                hs1 = __hadd2(hs1, __hadd2(*(__half2*)&pa[kc][1], *(__half2*)&pa[kc][3]));
            }
            float2 f0 = __half22float2(hs0), f1 = __half22float2(hs1);
            float s0 = f0.x + f0.y, s1 = f1.x + f1.y;
            s0 += __shfl_xor_sync(0xffffffffu, s0, 1);
            s0 += __shfl_xor_sync(0xffffffffu, s0, 2);
            s1 += __shfl_xor_sync(0xffffffffu, s1, 1);
            s1 += __shfl_xor_sync(0xffffffffu, s1, 2);
            l0r = l0r * al0 + s0;
            l1r = l1r * al1 + s1;

#pragma unroll
            for (int nb = 0; nb < 8; nb++) {
                oacc[nb][0] *= al0; oacc[nb][1] *= al0;
                oacc[nb][2] *= al1; oacc[nb][3] *= al1;
            }

            // ---- O += P @ Vt ----
#pragma unroll
            for (int kc = 0; kc < 4; kc++) {
#pragma unroll
                for (int nb = 0; nb < 8; nb++) {
                    uint32_t vb0 = Vb[(nb * 8 + g) * (FLD / 2) + kc * 8 + q];
                    uint32_t vb1 = Vb[(nb * 8 + g) * (FLD / 2) + kc * 8 + q + 4];
                    mma_f16(oacc[nb], pa[kc], vb0, vb1);
                }
            }

            buf = (buf + 1 >= 3) ? 0 : buf + 1;
        }
#undef FL_PREFETCH

        // ---- normalize + write merged [b, q, h*64+d] as fp16 ----
        float inv0 = 1.0f / l0r, inv1 = 1.0f / l1r;
        int r0 = q0 + wid * 16 + g;
        uint32_t* og0 = (uint32_t*)(g_attn + ((size_t)(b * SQ + r0) * DMODEL) + h * DHEAD);
        uint32_t* og1 = (uint32_t*)(g_attn + ((size_t)(b * SQ + r0 + 8) * DMODEL) + h * DHEAD);
#pragma unroll
        for (int nb = 0; nb < 8; nb++) {
            og0[nb * 4 + q] = pack_f16x2(oacc[nb][1] * inv0, oacc[nb][0] * inv0);
            og1[nb * 4 + q] = pack_f16x2(oacc[nb][3] * inv1, oacc[nb][2] * inv1);
        }
    }
}

// ---------------------------------------------------------------------------
// Launch
// ---------------------------------------------------------------------------
extern "C" void kernel_launch(void* const* d_in, const int* in_sizes, int n_in,
                              void* d_out, int out_size)
{
    const float* q  = (const float*)d_in[0];
    const float* k  = (const float*)d_in[1];
    const float* v  = (const float*)d_in[2];
    const float* Wq = (const float*)d_in[3];
    const float* bq = (const float*)d_in[4];
    const float* Wk = (const float*)d_in[5];
    const float* bk = (const float*)d_in[6];
    const float* Wv = (const float*)d_in[7];
    const float* bv = (const float*)d_in[8];
    const float* Wo = (const float*)d_in[9];
    const float* bo = (const float*)d_in[10];
    float* out = (float*)d_out;

    static bool attr_done = false;
    if (!attr_done) {
        cudaFuncSetAttribute(gemm_f16_kernel<0>, cudaFuncAttributeMaxDynamicSharedMemorySize, GEMM_SMEM);
        cudaFuncSetAttribute(gemm_f16_kernel<1>, cudaFuncAttributeMaxDynamicSharedMemorySize, GEMM_SMEM);
        cudaFuncSetAttribute(flash_attn_kernel, cudaFuncAttributeMaxDynamicSharedMemorySize, FLASH_SMEM);
        attr_done = true;
    }

    // 1. Convert inputs + weights to fp16
    {
        dim3 cgrid(4096, 7);
        preconvert_kernel<<<cgrid, 256>>>((const float4*)q, (const float4*)k, (const float4*)v,
                                          (const float4*)Wq, (const float4*)Wk,
                                          (const float4*)Wv, (const float4*)Wo);
    }

    // 2. Q/K/V projections in ONE single-wave 256-CTA grid (z-loop inside)
    {
        dim3 ggrid(DMODEL / 128, MROWS / 128);      // (8, 32) = 256 CTAs
        gemm_f16_kernel<0><<<ggrid, 256, GEMM_SMEM>>>(bq, bk, bv, nullptr);
    }

    // 3. Flash attention, single wave (batch loop inside)
    {
        dim3 fgrid(SQ / 128, NHEADS);               // (16, 16) = 256 CTAs
        flash_attn_kernel<<<fgrid, 256, FLASH_SMEM>>>();
    }

    // 4. Output projection
    {
        dim3 ggrid(DMODEL / 128, MROWS / 128);      // (8, 32)
        gemm_f16_kernel<1><<<ggrid, 256, GEMM_SMEM>>>(bo, nullptr, nullptr, out);
    }
}

// round 16
// speedup vs baseline: 1.0751x; 1.0751x over previous
#include <cuda_runtime.h>
#include <cuda_fp16.h>
#include <math_constants.h>
#include <cstdint>

#define DMODEL 1024
#define NHEADS 16
#define DHEAD  64
#define NBATCH 2
#define SQ     2048
#define SK     2048
#define MROWS  (NBATCH * SQ)   // 4096

// Q pre-scale: 1/sqrt(64) * log2(e)  (flash uses exp2)
#define QSCALE 0.18033688011112042f

// ---------------------------------------------------------------------------
// Scratch (device globals: no allocation allowed)
// ---------------------------------------------------------------------------
__device__ __half g_qh[(size_t)NBATCH * NHEADS * SQ * DHEAD];   // [b,h,q,d], pre-scaled
__device__ __half g_kh[(size_t)NBATCH * NHEADS * SK * DHEAD];   // [b,h,s,d]
__device__ __half g_vt[(size_t)NBATCH * NHEADS * DHEAD * SK];   // [b,h,d,s]  TRANSPOSED
__device__ __half g_attn[(size_t)NBATCH * SQ * DMODEL];          // [b,q,h*64+d]
__device__ __half g_act[(size_t)3 * MROWS * DMODEL];             // fp16(q,k,v)
__device__ __half g_w[(size_t)3 * DMODEL * DMODEL];              // fp16(Wq,Wk,Wv)  [k][n]
__device__ __half g_wo[(size_t)DMODEL * DMODEL];                 // fp16(Wo)        [k][n]

// ---------------------------------------------------------------------------
// helpers
// ---------------------------------------------------------------------------
__device__ __forceinline__ void cp_async16(void* smem, const void* gmem) {
    uint32_t s = (uint32_t)__cvta_generic_to_shared(smem);
    asm volatile("cp.async.cg.shared.global [%0], [%1], 16;\n" :: "r"(s), "l"(gmem));
}
__device__ __forceinline__ void cp_commit() { asm volatile("cp.async.commit_group;\n"); }
template<int N> __device__ __forceinline__ void cp_wait() {
    asm volatile("cp.async.wait_group %0;\n" :: "n"(N));
}
__device__ __forceinline__ uint32_t pack_f16x2(float hi, float lo) {
    uint32_t r; asm("cvt.rn.f16x2.f32 %0, %1, %2;" : "=r"(r) : "f"(hi), "f"(lo)); return r;
}
__device__ __forceinline__ uint32_t h2exp2(uint32_t x) {
    uint32_t r; asm("ex2.approx.f16x2 %0, %1;" : "=r"(r) : "r"(x)); return r;
}
__device__ __forceinline__ void mma_f16(float c[4], const uint32_t a[4], uint32_t b0, uint32_t b1) {
    asm volatile("mma.sync.aligned.m16n8k16.row.col.f32.f16.f16.f32 "
        "{%0,%1,%2,%3}, {%4,%5,%6,%7}, {%8,%9}, {%0,%1,%2,%3};\n"
        : "+f"(c[0]), "+f"(c[1]), "+f"(c[2]), "+f"(c[3])
        : "r"(a[0]), "r"(a[1]), "r"(a[2]), "r"(a[3]), "r"(b0), "r"(b1));
}
__device__ __forceinline__ void ldsm_x4(uint32_t& r0, uint32_t& r1,
                                        uint32_t& r2, uint32_t& r3, uint32_t addr) {
    asm volatile("ldmatrix.sync.aligned.m8n8.x4.shared.b16 {%0,%1,%2,%3}, [%4];"
        : "=r"(r0), "=r"(r1), "=r"(r2), "=r"(r3) : "r"(addr));
}
__device__ __forceinline__ void ldsm_x4_trans(uint32_t& r0, uint32_t& r1,
                                              uint32_t& r2, uint32_t& r3, uint32_t addr) {
    asm volatile("ldmatrix.sync.aligned.m8n8.x4.trans.shared.b16 {%0,%1,%2,%3}, [%4];"
        : "=r"(r0), "=r"(r1), "=r"(r2), "=r"(r3) : "r"(addr));
}
__device__ __forceinline__ uint32_t smem_u32(const void* p) {
    return (uint32_t)__cvta_generic_to_shared(p);
}

// ---------------------------------------------------------------------------
// Preconvert: inputs + weights -> fp16. Flat exact-fit grid: 16384 x 256
// (3 x 1048576 activation float4s + 4 x 262144 weight float4s).
// ---------------------------------------------------------------------------
#define PC_NA (MROWS * DMODEL / 4)     // 1048576 float4 per activation tensor
#define PC_NW (DMODEL * DMODEL / 4)    // 262144 float4 per weight matrix

__global__ __launch_bounds__(256)
void preconvert_kernel(const float4* __restrict__ q, const float4* __restrict__ k,
                       const float4* __restrict__ v, const float4* __restrict__ wq,
                       const float4* __restrict__ wk, const float4* __restrict__ wv,
                       const float4* __restrict__ wo)
{
    int idx = blockIdx.x * 256 + threadIdx.x;
    const float4* src;
    __half* dst;
    int off;
    if (idx < 3 * PC_NA) {
        int t = idx / PC_NA;
        off = idx - t * PC_NA;
        src = (t == 0) ? q : (t == 1) ? k : v;
        dst = g_act + (size_t)t * (MROWS * DMODEL);
    } else {
        int j = idx - 3 * PC_NA;
        int t = j / PC_NW;
        off = j - t * PC_NW;
        src = (t == 0) ? wq : (t == 1) ? wk : (t == 2) ? wv : wo;
        dst = (t < 3) ? g_w + (size_t)t * (DMODEL * DMODEL) : g_wo;
    }
    float4 s = src[off];
    uint2 u;
    u.x = pack_f16x2(s.y, s.x);
    u.y = pack_f16x2(s.w, s.z);
    *(uint2*)(dst + 4 * (size_t)off) = u;
}

// ---------------------------------------------------------------------------
// FP16 GEMM v4: manual mma + ldmatrix, BK=64 (16 iterations, half the
// barriers of BK=32), 3-stage cp.async pipeline, CTA 128x128, 8 warps
// (warp tile 32x64), fp32 accum, direct-to-global epilogue.
// MODE 0: batched projections (z: 0->g_qh x QSCALE, 1->g_kh, 2->g_vt transposed)
// MODE 1: out = g_attn @ g_wo + bo (fp32)
// ---------------------------------------------------------------------------
#define G_ALD 72     // halves per A row (64 + 8 pad)
#define G_BLD 136    // halves per B row (128 + 8 pad)
#define G_ASZ (128 * G_ALD)   // 9216 halves
#define G_BSZ (64 * G_BLD)    // 8704 halves
#define GEMM_SMEM (3 * (G_ASZ + G_BSZ) * (int)sizeof(__half))  // 107520

template<int MODE>
__global__ __launch_bounds__(256, 2)
void gemm_f16_kernel(const float* __restrict__ bias0,
                     const float* __restrict__ bias1,
                     const float* __restrict__ bias2,
                     float* __restrict__ out)
{
    extern __shared__ __half gsm[];
    __half* Asm = gsm;                  // [3][128][72]
    __half* Bsm = gsm + 3 * G_ASZ;      // [3][64][136]

    const int z = blockIdx.z;
    const __half* Ap   = (MODE == 1) ? g_attn : g_act + (size_t)z * (MROWS * DMODEL);
    const __half* W    = (MODE == 1) ? g_wo   : g_w   + (size_t)z * (DMODEL * DMODEL);
    const float* bias  = (MODE == 1) ? bias0  : (z == 0) ? bias0 : (z == 1) ? bias1 : bias2;

    const int tid    = threadIdx.x;
    const int wid    = tid >> 5;
    const int lane   = tid & 31;
    const int warp_m = wid >> 1;     // 0..3 (32 rows each)
    const int warp_n = wid & 1;      // 0..1 (64 cols each)
    const int m0 = blockIdx.y * 128;
    const int n0 = blockIdx.x * 128;

    float acc[2][8][4];
#pragma unroll
    for (int i = 0; i < 2; i++)
#pragma unroll
        for (int j = 0; j < 8; j++)
#pragma unroll
            for (int t = 0; t < 4; t++) acc[i][j][t] = 0.0f;

    const uint32_t a_lane = (uint32_t)((warp_m * 32 + (lane & 15)) * G_ALD + (lane >> 4) * 8) * 2;
    const uint32_t b_lane = (uint32_t)((((lane >> 3) & 1) * 8 + (lane & 7)) * G_BLD
                                       + warp_n * 64 + (lane >> 4) * 8) * 2;

#define GEMM_PREFETCH(IT, BUF)                                                      \
    {                                                                               \
        int k0 = (IT) * 64;                                                         \
        _Pragma("unroll")                                                           \
        for (int i = 0; i < 4; i++) {                                               \
            int idx = tid + i * 256;                                                \
            int r = idx >> 3, c = idx & 7;                                          \
            cp_async16(&Asm[(BUF) * G_ASZ + r * G_ALD + c * 8],                     \
                       Ap + (size_t)(m0 + r) * DMODEL + k0 + c * 8);                \
        }                                                                           \
        _Pragma("unroll")                                                           \
        for (int i = 0; i < 4; i++) {                                               \
            int idx = tid + i * 256;                                                \
            int r = idx >> 4, c = idx & 15;                                         \
            cp_async16(&Bsm[(BUF) * G_BSZ + r * G_BLD + c * 8],                     \
                       W + (size_t)(k0 + r) * DMODEL + n0 + c * 8);                 \
        }                                                                           \
        cp_commit();                                                                \
    }

    GEMM_PREFETCH(0, 0);
    GEMM_PREFETCH(1, 1);

    int buf = 0;
    for (int it = 0; it < 16; it++) {
        if (it + 1 < 16) cp_wait<1>(); else cp_wait<0>();
        __syncthreads();
        if (it + 2 < 16) {
            int nbuf = (buf + 2 >= 3) ? buf - 1 : buf + 2;
            GEMM_PREFETCH(it + 2, nbuf);
        }

        const uint32_t abase = smem_u32(Asm + buf * G_ASZ) + a_lane;
        const uint32_t bbase = smem_u32(Bsm + buf * G_BSZ) + b_lane;

#pragma unroll
        for (int kc = 0; kc < 4; kc++) {
            uint32_t a[2][4];
            ldsm_x4(a[0][0], a[0][1], a[0][2], a[0][3], abase + kc * 32);
            ldsm_x4(a[1][0], a[1][1], a[1][2], a[1][3], abase + kc * 32 + 16 * G_ALD * 2);
#pragma unroll
            for (int ni2 = 0; ni2 < 4; ni2++) {
                uint32_t b0, b1, b2, b3;
                ldsm_x4_trans(b0, b1, b2, b3, bbase + kc * (16 * G_BLD * 2) + ni2 * 32);
                mma_f16(acc[0][2 * ni2],     a[0], b0, b1);
                mma_f16(acc[1][2 * ni2],     a[1], b0, b1);
                mma_f16(acc[0][2 * ni2 + 1], a[0], b2, b3);
                mma_f16(acc[1][2 * ni2 + 1], a[1], b2, b3);
            }
        }
        buf = (buf + 1 >= 3) ? 0 : buf + 1;
    }
#undef GEMM_PREFETCH

    // ---- direct epilogue (c0/c1 pairs -> contiguous cols) ----
    const int g  = lane >> 2;
    const int qq = lane & 3;
#pragma unroll
    for (int mi = 0; mi < 2; mi++) {
        const int r0 = m0 + warp_m * 32 + mi * 16 + g;
#pragma unroll
        for (int ni = 0; ni < 8; ni++) {
            const int col = n0 + warp_n * 64 + ni * 8 + 2 * qq;
            const float bv0 = bias[col], bv1 = bias[col + 1];
            float v0 = acc[mi][ni][0] + bv0, v1 = acc[mi][ni][1] + bv1;
            float v2 = acc[mi][ni][2] + bv0, v3 = acc[mi][ni][3] + bv1;
#pragma unroll
            for (int half = 0; half < 2; half++) {
                const int grow = r0 + half * 8;
                const float w0 = half ? v2 : v0;
                const float w1 = half ? v3 : v1;
                if (MODE == 0) {
                    int b_ = grow >> 11, qr = grow & 2047;
                    int h_ = col >> 6, d_ = col & 63;
                    if (z == 0) {
                        size_t a = (((size_t)(b_ * NHEADS + h_) * SQ) + qr) * DHEAD + d_;
                        *(uint32_t*)(g_qh + a) = pack_f16x2(w1 * QSCALE, w0 * QSCALE);
                    } else if (z == 1) {
                        size_t a = (((size_t)(b_ * NHEADS + h_) * SK) + qr) * DHEAD + d_;
                        *(uint32_t*)(g_kh + a) = pack_f16x2(w1, w0);
                    } else {
                        size_t a = (((size_t)(b_ * NHEADS + h_) * DHEAD) + d_) * SK + qr;
                        g_vt[a] = __float2half(w0);
                        g_vt[a + SK] = __float2half(w1);
                    }
                } else {
                    *(float2*)(out + (size_t)grow * DMODEL + col) = make_float2(w0, w1);
                }
            }
        }
    }
}

// ---------------------------------------------------------------------------
// Flash attention fp16 (R14 best form, unchanged): register-resident S/O,
// mma.m16n8k16, triple-buffered K/Vt tiles, f16x2 softmax exponentials.
// ---------------------------------------------------------------------------
#define FLD 72                       // halves per row (64 + 8 pad)
#define FL_TSZ (64 * FLD)            // halves per tile
#define FLASH_SMEM ((6 * FL_TSZ) * (int)sizeof(__half))   // 55296

__global__ __launch_bounds__(256)
void flash_attn_kernel()
{
    extern __shared__ __half fsm[];
    __half* Ksm = fsm;                 // [3][64][FLD]; bufs 0-1 double as Q staging
    __half* Vsm = fsm + 3 * FL_TSZ;    // [3][64][FLD]

    const int q0  = blockIdx.x * 128;
    const int h   = blockIdx.y;
    const int b   = blockIdx.z;
    const int tid = threadIdx.x;
    const int wid = tid >> 5;
    const int lane = tid & 31;
    const int g = lane >> 2;
    const int q = lane & 3;

    const __half* Qg = g_qh + (((size_t)(b * NHEADS + h) * SQ) + q0) * DHEAD;
    const __half* Kg = g_kh + ((size_t)(b * NHEADS + h) * SK) * DHEAD;
    const __half* Vg = g_vt + ((size_t)(b * NHEADS + h) * DHEAD) * SK;

    // ---- Stage Q tile (128 x 64 halves) into Ksm bufs 0-1, build A frags ----
#pragma unroll
    for (int i = 0; i < 4; i++) {
        int idx = tid + i * 256;
        int r = idx >> 3, c = idx & 7;
        cp_async16(&Ksm[r * FLD + c * 8], Qg + (size_t)r * DHEAD + c * 8);
    }
    cp_commit();
    cp_wait<0>();
    __syncthreads();

    uint32_t qa[4][4];
    {
        const uint32_t* Qw = (const uint32_t*)Ksm;
        const int r0 = wid * 16 + g;
#pragma unroll
        for (int kc = 0; kc < 4; kc++) {
            qa[kc][0] = Qw[(r0)     * (FLD / 2) + kc * 8 + q];
            qa[kc][1] = Qw[(r0 + 8) * (FLD / 2) + kc * 8 + q];
            qa[kc][2] = Qw[(r0)     * (FLD / 2) + kc * 8 + q + 4];
            qa[kc][3] = Qw[(r0 + 8) * (FLD / 2) + kc * 8 + q + 4];
        }
    }
    __syncthreads();   // everyone done reading Q before K overwrites

#define FL_PREFETCH(J, BUF)                                                         \
    {                                                                               \
        _Pragma("unroll")                                                           \
        for (int i = 0; i < 2; i++) {                                               \
            int idx = tid + i * 256;                                                \
            int r = idx >> 3, c = idx & 7;                                          \
            cp_async16(&Ksm[(BUF) * FL_TSZ + r * FLD + c * 8],                      \
                       Kg + (size_t)((J) * 64 + r) * DHEAD + c * 8);                \
            cp_async16(&Vsm[(BUF) * FL_TSZ + r * FLD + c * 8],                      \
                       Vg + (size_t)r * SK + (J) * 64 + c * 8);                     \
        }                                                                           \
        cp_commit();                                                                \
    }

    FL_PREFETCH(0, 0);
    FL_PREFETCH(1, 1);

    float oacc[8][4];
#pragma unroll
    for (int nb = 0; nb < 8; nb++)
#pragma unroll
        for (int t = 0; t < 4; t++) oacc[nb][t] = 0.0f;

    float m0r = -CUDART_INF_F, m1r = -CUDART_INF_F;
    float l0r = 0.0f, l1r = 0.0f;

    const int NT = SK / 64;  // 32
    int buf = 0;
    for (int j = 0; j < NT; j++) {
        if (j + 1 < NT) cp_wait<1>(); else cp_wait<0>();
        __syncthreads();
        if (j + 2 < NT) {
            int nbuf = (buf + 2 >= 3) ? buf - 1 : buf + 2;
            FL_PREFETCH(j + 2, nbuf);
        }

        const uint32_t* Kb = (const uint32_t*)(Ksm + buf * FL_TSZ);
        const uint32_t* Vb = (const uint32_t*)(Vsm + buf * FL_TSZ);

        // ---- S (log2-domain logits; Q pre-scaled) ----
        float sacc[8][4];
#pragma unroll
        for (int nb = 0; nb < 8; nb++) {
#pragma unroll
            for (int t = 0; t < 4; t++) sacc[nb][t] = 0.0f;
#pragma unroll
            for (int kc = 0; kc < 4; kc++) {
                uint32_t b0 = Kb[(nb * 8 + g) * (FLD / 2) + kc * 8 + q];
                uint32_t b1 = Kb[(nb * 8 + g) * (FLD / 2) + kc * 8 + q + 4];
                mma_f16(sacc[nb], qa[kc], b0, b1);
            }
        }

        // ---- online softmax: row maxima (fp32), P = f16x2 exp2 ----
        float mx0 = -CUDART_INF_F, mx1 = -CUDART_INF_F;
#pragma unroll
        for (int nb = 0; nb < 8; nb++) {
            mx0 = fmaxf(mx0, fmaxf(sacc[nb][0], sacc[nb][1]));
            mx1 = fmaxf(mx1, fmaxf(sacc[nb][2], sacc[nb][3]));
        }
        mx0 = fmaxf(mx0, __shfl_xor_sync(0xffffffffu, mx0, 1));
        mx0 = fmaxf(mx0, __shfl_xor_sync(0xffffffffu, mx0, 2));
        mx1 = fmaxf(mx1, __shfl_xor_sync(0xffffffffu, mx1, 1));
        mx1 = fmaxf(mx1, __shfl_xor_sync(0xffffffffu, mx1, 2));

        float mn0 = fmaxf(m0r, mx0), mn1 = fmaxf(m1r, mx1);
        float al0 = exp2f(m0r - mn0), al1 = exp2f(m1r - mn1);
        m0r = mn0; m1r = mn1;

        uint32_t pa[4][4];
        __half2 hs0 = __float2half2_rn(0.0f), hs1 = __float2half2_rn(0.0f);
#pragma unroll
        for (int kc = 0; kc < 4; kc++) {
            pa[kc][0] = h2exp2(pack_f16x2(sacc[2 * kc][1] - mn0,     sacc[2 * kc][0] - mn0));
            pa[kc][1] = h2exp2(pack_f16x2(sacc[2 * kc][3] - mn1,     sacc[2 * kc][2] - mn1));
            pa[kc][2] = h2exp2(pack_f16x2(sacc[2 * kc + 1][1] - mn0, sacc[2 * kc + 1][0] - mn0));
            pa[kc][3] = h2exp2(pack_f16x2(sacc[2 * kc + 1][3] - mn1, sacc[2 * kc + 1][2] - mn1));
            hs0 = __hadd2(hs0, __hadd2(*(__half2*)&pa[kc][0], *(__half2*)&pa[kc][2]));
            hs1 = __hadd2(hs1, __hadd2(*(__half2*)&pa[kc][1], *(__half2*)&pa[kc][3]));
        }
        float2 f0 = __half22float2(hs0), f1 = __half22float2(hs1);
        float s0 = f0.x + f0.y, s1 = f1.x + f1.y;
        s0 += __shfl_xor_sync(0xffffffffu, s0, 1);
        s0 += __shfl_xor_sync(0xffffffffu, s0, 2);
        s1 += __shfl_xor_sync(0xffffffffu, s1, 1);
        s1 += __shfl_xor_sync(0xffffffffu, s1, 2);
        l0r = l0r * al0 + s0;
        l1r = l1r * al1 + s1;

#pragma unroll
        for (int nb = 0; nb < 8; nb++) {
            oacc[nb][0] *= al0; oacc[nb][1] *= al0;
            oacc[nb][2] *= al1; oacc[nb][3] *= al1;
        }

        // ---- O += P @ Vt ----
#pragma unroll
        for (int kc = 0; kc < 4; kc++) {
#pragma unroll
            for (int nb = 0; nb < 8; nb++) {
                uint32_t vb0 = Vb[(nb * 8 + g) * (FLD / 2) + kc * 8 + q];
                uint32_t vb1 = Vb[(nb * 8 + g) * (FLD / 2) + kc * 8 + q + 4];
                mma_f16(oacc[nb], pa[kc], vb0, vb1);
            }
        }

        buf = (buf + 1 >= 3) ? 0 : buf + 1;
    }
#undef FL_PREFETCH

    // ---- normalize + write merged [b, q, h*64+d] as fp16 ----
    float inv0 = 1.0f / l0r, inv1 = 1.0f / l1r;
    int r0 = q0 + wid * 16 + g;
    uint32_t* og0 = (uint32_t*)(g_attn + ((size_t)(b * SQ + r0) * DMODEL) + h * DHEAD);
    uint32_t* og1 = (uint32_t*)(g_attn + ((size_t)(b * SQ + r0 + 8) * DMODEL) + h * DHEAD);
#pragma unroll
    for (int nb = 0; nb < 8; nb++) {
        og0[nb * 4 + q] = pack_f16x2(oacc[nb][1] * inv0, oacc[nb][0] * inv0);
        og1[nb * 4 + q] = pack_f16x2(oacc[nb][3] * inv1, oacc[nb][2] * inv1);
    }
}

// ---------------------------------------------------------------------------
// Launch (R14 structure: multi-wave grids, scheduler absorbs tails)
// ---------------------------------------------------------------------------
extern "C" void kernel_launch(void* const* d_in, const int* in_sizes, int n_in,
                              void* d_out, int out_size)
{
    const float* q  = (const float*)d_in[0];
    const float* k  = (const float*)d_in[1];
    const float* v  = (const float*)d_in[2];
    const float* Wq = (const float*)d_in[3];
    const float* bq = (const float*)d_in[4];
    const float* Wk = (const float*)d_in[5];
    const float* bk = (const float*)d_in[6];
    const float* Wv = (const float*)d_in[7];
    const float* bv = (const float*)d_in[8];
    const float* Wo = (const float*)d_in[9];
    const float* bo = (const float*)d_in[10];
    float* out = (float*)d_out;

    static bool attr_done = false;
    if (!attr_done) {
        cudaFuncSetAttribute(gemm_f16_kernel<0>, cudaFuncAttributeMaxDynamicSharedMemorySize, GEMM_SMEM);
        cudaFuncSetAttribute(gemm_f16_kernel<1>, cudaFuncAttributeMaxDynamicSharedMemorySize, GEMM_SMEM);
        cudaFuncSetAttribute(flash_attn_kernel, cudaFuncAttributeMaxDynamicSharedMemorySize, FLASH_SMEM);
        attr_done = true;
    }

    // 1. Convert inputs + weights to fp16 (flat exact-fit grid)
    {
        preconvert_kernel<<<16384, 256>>>((const float4*)q, (const float4*)k, (const float4*)v,
                                          (const float4*)Wq, (const float4*)Wk,
                                          (const float4*)Wv, (const float4*)Wo);
    }

    // 2. Batched Q/K/V projections -> head-major fp16 scratch (V transposed)
    {
        dim3 ggrid(DMODEL / 128, MROWS / 128, 3);   // (8, 32, 3)
        gemm_f16_kernel<0><<<ggrid, 256, GEMM_SMEM>>>(bq, bk, bv, nullptr);
    }

    // 3. Flash attention
    {
        dim3 fgrid(SQ / 128, NHEADS, NBATCH);       // (16, 16, 2)
        flash_attn_kernel<<<fgrid, 256, FLASH_SMEM>>>();
    }

    // 4. Output projection
    {
        dim3 ggrid(DMODEL / 128, MROWS / 128, 1);   // (8, 32)
        gemm_f16_kernel<1><<<ggrid, 256, GEMM_SMEM>>>(bo, nullptr, nullptr, out);
    }
}

// round 17
// speedup vs baseline: 1.1182x; 1.0401x over previous
#include <cuda_runtime.h>
#include <cuda_fp16.h>
#include <math_constants.h>
#include <cstdint>

#define DMODEL 1024
#define NHEADS 16
#define DHEAD  64
#define NBATCH 2
#define SQ     2048
#define SK     2048
#define MROWS  (NBATCH * SQ)   // 4096

// Q pre-scale: 1/sqrt(64) * log2(e)  (flash uses exp2)
#define QSCALE 0.18033688011112042f

// ---------------------------------------------------------------------------
// Scratch (device globals: no allocation allowed)
// ---------------------------------------------------------------------------
__device__ __half g_qh[(size_t)NBATCH * NHEADS * SQ * DHEAD];   // [b,h,q,d], pre-scaled
__device__ __half g_kh[(size_t)NBATCH * NHEADS * SK * DHEAD];   // [b,h,s,d]
__device__ __half g_vt[(size_t)NBATCH * NHEADS * DHEAD * SK];   // [b,h,d,s]  TRANSPOSED
__device__ __half g_attn[(size_t)NBATCH * SQ * DMODEL];          // [b,q,h*64+d]
__device__ __half g_act[(size_t)3 * MROWS * DMODEL];             // fp16(q,k,v)
__device__ __half g_w[(size_t)3 * DMODEL * DMODEL];              // fp16(Wq,Wk,Wv)  [k][n]
__device__ __half g_wo[(size_t)DMODEL * DMODEL];                 // fp16(Wo)        [k][n]

// ---------------------------------------------------------------------------
// helpers
// ---------------------------------------------------------------------------
__device__ __forceinline__ void cp_async16(void* smem, const void* gmem) {
    uint32_t s = (uint32_t)__cvta_generic_to_shared(smem);
    asm volatile("cp.async.cg.shared.global [%0], [%1], 16;\n" :: "r"(s), "l"(gmem));
}
__device__ __forceinline__ void cp_commit() { asm volatile("cp.async.commit_group;\n"); }
template<int N> __device__ __forceinline__ void cp_wait() {
    asm volatile("cp.async.wait_group %0;\n" :: "n"(N));
}
__device__ __forceinline__ uint32_t pack_f16x2(float hi, float lo) {
    uint32_t r; asm("cvt.rn.f16x2.f32 %0, %1, %2;" : "=r"(r) : "f"(hi), "f"(lo)); return r;
}
__device__ __forceinline__ uint32_t h2exp2(uint32_t x) {
    uint32_t r; asm("ex2.approx.f16x2 %0, %1;" : "=r"(r) : "r"(x)); return r;
}
__device__ __forceinline__ void mma_f16(float c[4], const uint32_t a[4], uint32_t b0, uint32_t b1) {
    asm volatile("mma.sync.aligned.m16n8k16.row.col.f32.f16.f16.f32 "
        "{%0,%1,%2,%3}, {%4,%5,%6,%7}, {%8,%9}, {%0,%1,%2,%3};\n"
        : "+f"(c[0]), "+f"(c[1]), "+f"(c[2]), "+f"(c[3])
        : "r"(a[0]), "r"(a[1]), "r"(a[2]), "r"(a[3]), "r"(b0), "r"(b1));
}
__device__ __forceinline__ void ldsm_x4(uint32_t& r0, uint32_t& r1,
                                        uint32_t& r2, uint32_t& r3, uint32_t addr) {
    asm volatile("ldmatrix.sync.aligned.m8n8.x4.shared.b16 {%0,%1,%2,%3}, [%4];"
        : "=r"(r0), "=r"(r1), "=r"(r2), "=r"(r3) : "r"(addr));
}
__device__ __forceinline__ void ldsm_x4_trans(uint32_t& r0, uint32_t& r1,
                                              uint32_t& r2, uint32_t& r3, uint32_t addr) {
    asm volatile("ldmatrix.sync.aligned.m8n8.x4.trans.shared.b16 {%0,%1,%2,%3}, [%4];"
        : "=r"(r0), "=r"(r1), "=r"(r2), "=r"(r3) : "r"(addr));
}
__device__ __forceinline__ uint32_t smem_u32(const void* p) {
    return (uint32_t)__cvta_generic_to_shared(p);
}

// ---------------------------------------------------------------------------
// Preconvert: inputs + weights -> fp16. Flat exact-fit grid: 16384 x 256.
// ---------------------------------------------------------------------------
#define PC_NA (MROWS * DMODEL / 4)     // 1048576 float4 per activation tensor
#define PC_NW (DMODEL * DMODEL / 4)    // 262144 float4 per weight matrix

__global__ __launch_bounds__(256)
void preconvert_kernel(const float4* __restrict__ q, const float4* __restrict__ k,
                       const float4* __restrict__ v, const float4* __restrict__ wq,
                       const float4* __restrict__ wk, const float4* __restrict__ wv,
                       const float4* __restrict__ wo)
{
    int idx = blockIdx.x * 256 + threadIdx.x;
    const float4* src;
    __half* dst;
    int off;
    if (idx < 3 * PC_NA) {
        int t = idx / PC_NA;
        off = idx - t * PC_NA;
        src = (t == 0) ? q : (t == 1) ? k : v;
        dst = g_act + (size_t)t * (MROWS * DMODEL);
    } else {
        int j = idx - 3 * PC_NA;
        int t = j / PC_NW;
        off = j - t * PC_NW;
        src = (t == 0) ? wq : (t == 1) ? wk : (t == 2) ? wv : wo;
        dst = (t < 3) ? g_w + (size_t)t * (DMODEL * DMODEL) : g_wo;
    }
    float4 s = src[off];
    uint2 u;
    u.x = pack_f16x2(s.y, s.x);
    u.y = pack_f16x2(s.w, s.z);
    *(uint2*)(dst + 4 * (size_t)off) = u;
}

// ---------------------------------------------------------------------------
// FP16 GEMM (R16 form, unchanged): manual mma + ldmatrix, BK=64, 3-stage
// cp.async, CTA 128x128, 8 warps (warp tile 32x64), fp32 accum,
// direct-to-global epilogue.
// ---------------------------------------------------------------------------
#define G_ALD 72     // halves per A row (64 + 8 pad)
#define G_BLD 136    // halves per B row (128 + 8 pad)
#define G_ASZ (128 * G_ALD)
#define G_BSZ (64 * G_BLD)
#define GEMM_SMEM (3 * (G_ASZ + G_BSZ) * (int)sizeof(__half))  // 107520

template<int MODE>
__global__ __launch_bounds__(256, 2)
void gemm_f16_kernel(const float* __restrict__ bias0,
                     const float* __restrict__ bias1,
                     const float* __restrict__ bias2,
                     float* __restrict__ out)
{
    extern __shared__ __half gsm[];
    __half* Asm = gsm;                  // [3][128][72]
    __half* Bsm = gsm + 3 * G_ASZ;      // [3][64][136]

    const int z = blockIdx.z;
    const __half* Ap   = (MODE == 1) ? g_attn : g_act + (size_t)z * (MROWS * DMODEL);
    const __half* W    = (MODE == 1) ? g_wo   : g_w   + (size_t)z * (DMODEL * DMODEL);
    const float* bias  = (MODE == 1) ? bias0  : (z == 0) ? bias0 : (z == 1) ? bias1 : bias2;

    const int tid    = threadIdx.x;
    const int wid    = tid >> 5;
    const int lane   = tid & 31;
    const int warp_m = wid >> 1;
    const int warp_n = wid & 1;
    const int m0 = blockIdx.y * 128;
    const int n0 = blockIdx.x * 128;

    float acc[2][8][4];
#pragma unroll
    for (int i = 0; i < 2; i++)
#pragma unroll
        for (int j = 0; j < 8; j++)
#pragma unroll
            for (int t = 0; t < 4; t++) acc[i][j][t] = 0.0f;

    const uint32_t a_lane = (uint32_t)((warp_m * 32 + (lane & 15)) * G_ALD + (lane >> 4) * 8) * 2;
    const uint32_t b_lane = (uint32_t)((((lane >> 3) & 1) * 8 + (lane & 7)) * G_BLD
                                       + warp_n * 64 + (lane >> 4) * 8) * 2;

#define GEMM_PREFETCH(IT, BUF)                                                      \
    {                                                                               \
        int k0 = (IT) * 64;                                                         \
        _Pragma("unroll")                                                           \
        for (int i = 0; i < 4; i++) {                                               \
            int idx = tid + i * 256;                                                \
            int r = idx >> 3, c = idx & 7;                                          \
            cp_async16(&Asm[(BUF) * G_ASZ + r * G_ALD + c * 8],                     \
                       Ap + (size_t)(m0 + r) * DMODEL + k0 + c * 8);                \
        }                                                                           \
        _Pragma("unroll")                                                           \
        for (int i = 0; i < 4; i++) {                                               \
            int idx = tid + i * 256;                                                \
            int r = idx >> 4, c = idx & 15;                                         \
            cp_async16(&Bsm[(BUF) * G_BSZ + r * G_BLD + c * 8],                     \
                       W + (size_t)(k0 + r) * DMODEL + n0 + c * 8);                 \
        }                                                                           \
        cp_commit();                                                                \
    }

    GEMM_PREFETCH(0, 0);
    GEMM_PREFETCH(1, 1);

    int buf = 0;
    for (int it = 0; it < 16; it++) {
        if (it + 1 < 16) cp_wait<1>(); else cp_wait<0>();
        __syncthreads();
        if (it + 2 < 16) {
            int nbuf = (buf + 2 >= 3) ? buf - 1 : buf + 2;
            GEMM_PREFETCH(it + 2, nbuf);
        }

        const uint32_t abase = smem_u32(Asm + buf * G_ASZ) + a_lane;
        const uint32_t bbase = smem_u32(Bsm + buf * G_BSZ) + b_lane;

#pragma unroll
        for (int kc = 0; kc < 4; kc++) {
            uint32_t a[2][4];
            ldsm_x4(a[0][0], a[0][1], a[0][2], a[0][3], abase + kc * 32);
            ldsm_x4(a[1][0], a[1][1], a[1][2], a[1][3], abase + kc * 32 + 16 * G_ALD * 2);
#pragma unroll
            for (int ni2 = 0; ni2 < 4; ni2++) {
                uint32_t b0, b1, b2, b3;
                ldsm_x4_trans(b0, b1, b2, b3, bbase + kc * (16 * G_BLD * 2) + ni2 * 32);
                mma_f16(acc[0][2 * ni2],     a[0], b0, b1);
                mma_f16(acc[1][2 * ni2],     a[1], b0, b1);
                mma_f16(acc[0][2 * ni2 + 1], a[0], b2, b3);
                mma_f16(acc[1][2 * ni2 + 1], a[1], b2, b3);
            }
        }
        buf = (buf + 1 >= 3) ? 0 : buf + 1;
    }
#undef GEMM_PREFETCH

    // ---- direct epilogue ----
    const int g  = lane >> 2;
    const int qq = lane & 3;
#pragma unroll
    for (int mi = 0; mi < 2; mi++) {
        const int r0 = m0 + warp_m * 32 + mi * 16 + g;
#pragma unroll
        for (int ni = 0; ni < 8; ni++) {
            const int col = n0 + warp_n * 64 + ni * 8 + 2 * qq;
            const float bv0 = bias[col], bv1 = bias[col + 1];
            float v0 = acc[mi][ni][0] + bv0, v1 = acc[mi][ni][1] + bv1;
            float v2 = acc[mi][ni][2] + bv0, v3 = acc[mi][ni][3] + bv1;
#pragma unroll
            for (int half = 0; half < 2; half++) {
                const int grow = r0 + half * 8;
                const float w0 = half ? v2 : v0;
                const float w1 = half ? v3 : v1;
                if (MODE == 0) {
                    int b_ = grow >> 11, qr = grow & 2047;
                    int h_ = col >> 6, d_ = col & 63;
                    if (z == 0) {
                        size_t a = (((size_t)(b_ * NHEADS + h_) * SQ) + qr) * DHEAD + d_;
                        *(uint32_t*)(g_qh + a) = pack_f16x2(w1 * QSCALE, w0 * QSCALE);
                    } else if (z == 1) {
                        size_t a = (((size_t)(b_ * NHEADS + h_) * SK) + qr) * DHEAD + d_;
                        *(uint32_t*)(g_kh + a) = pack_f16x2(w1, w0);
                    } else {
                        size_t a = (((size_t)(b_ * NHEADS + h_) * DHEAD) + d_) * SK + qr;
                        g_vt[a] = __float2half(w0);
                        g_vt[a + SK] = __float2half(w1);
                    }
                } else {
                    *(float2*)(out + (size_t)grow * DMODEL + col) = make_float2(w0, w1);
                }
            }
        }
    }
}

// ---------------------------------------------------------------------------
// Flash attention v5: 32 q-rows per warp (two m16 row-groups SHARING every
// K/V fragment load -> 1 LDS per MMA instead of 2), CTA covers 256 q-rows,
// 8 warps, triple-buffered K/Vt, f16x2 softmax exponentials.
// ---------------------------------------------------------------------------
#define FLD 72                       // halves per row (64 + 8 pad)
#define FL_TSZ (64 * FLD)            // halves per tile
#define FLASH_SMEM ((6 * FL_TSZ) * (int)sizeof(__half))   // 55296

__global__ __launch_bounds__(256)
void flash_attn_kernel()
{
    extern __shared__ __half fsm[];
    __half* Ksm = fsm;                 // [3][64][FLD]
    __half* Vsm = fsm + 3 * FL_TSZ;    // [3][64][FLD]

    const int q0  = blockIdx.x * 256;
    const int h   = blockIdx.y;
    const int b   = blockIdx.z;
    const int tid = threadIdx.x;
    const int wid = tid >> 5;
    const int lane = tid & 31;
    const int g = lane >> 2;
    const int q = lane & 3;

    const __half* Qg = g_qh + (((size_t)(b * NHEADS + h) * SQ) + q0) * DHEAD;
    const __half* Kg = g_kh + ((size_t)(b * NHEADS + h) * SK) * DHEAD;
    const __half* Vg = g_vt + ((size_t)(b * NHEADS + h) * DHEAD) * SK;

    // ---- Stage Q tile (256 x 64 halves) across fsm[0..18432) ----
#pragma unroll
    for (int i = 0; i < 8; i++) {
        int idx = tid + i * 256;
        int r = idx >> 3, c = idx & 7;
        cp_async16(&fsm[r * FLD + c * 8], Qg + (size_t)r * DHEAD + c * 8);
    }
    cp_commit();
    cp_wait<0>();
    __syncthreads();

    uint32_t qa[2][4][4];
    {
        const uint32_t* Qw = (const uint32_t*)fsm;
#pragma unroll
        for (int G = 0; G < 2; G++) {
            const int r0 = wid * 32 + G * 16 + g;
#pragma unroll
            for (int kc = 0; kc < 4; kc++) {
                qa[G][kc][0] = Qw[(r0)     * (FLD / 2) + kc * 8 + q];
                qa[G][kc][1] = Qw[(r0 + 8) * (FLD / 2) + kc * 8 + q];
                qa[G][kc][2] = Qw[(r0)     * (FLD / 2) + kc * 8 + q + 4];
                qa[G][kc][3] = Qw[(r0 + 8) * (FLD / 2) + kc * 8 + q + 4];
            }
        }
    }
    __syncthreads();   // everyone done reading Q before K/V stages overwrite

#define FL_PREFETCH(J, BUF)                                                         \
    {                                                                               \
        _Pragma("unroll")                                                           \
        for (int i = 0; i < 2; i++) {                                               \
            int idx = tid + i * 256;                                                \
            int r = idx >> 3, c = idx & 7;                                          \
            cp_async16(&Ksm[(BUF) * FL_TSZ + r * FLD + c * 8],                      \
                       Kg + (size_t)((J) * 64 + r) * DHEAD + c * 8);                \
            cp_async16(&Vsm[(BUF) * FL_TSZ + r * FLD + c * 8],                      \
                       Vg + (size_t)r * SK + (J) * 64 + c * 8);                     \
        }                                                                           \
        cp_commit();                                                                \
    }

    FL_PREFETCH(0, 0);
    FL_PREFETCH(1, 1);

    float oacc[2][8][4];
#pragma unroll
    for (int G = 0; G < 2; G++)
#pragma unroll
        for (int nb = 0; nb < 8; nb++)
#pragma unroll
            for (int t = 0; t < 4; t++) oacc[G][nb][t] = 0.0f;

    float m0r[2] = {-CUDART_INF_F, -CUDART_INF_F};
    float m1r[2] = {-CUDART_INF_F, -CUDART_INF_F};
    float l0r[2] = {0.0f, 0.0f};
    float l1r[2] = {0.0f, 0.0f};

    const int NT = SK / 64;  // 32
    int buf = 0;
    for (int j = 0; j < NT; j++) {
        if (j + 1 < NT) cp_wait<1>(); else cp_wait<0>();
        __syncthreads();
        if (j + 2 < NT) {
            int nbuf = (buf + 2 >= 3) ? buf - 1 : buf + 2;
            FL_PREFETCH(j + 2, nbuf);
        }

        const uint32_t* Kb = (const uint32_t*)(Ksm + buf * FL_TSZ);
        const uint32_t* Vb = (const uint32_t*)(Vsm + buf * FL_TSZ);

        // ---- S: both row-groups share each K fragment load ----
        float sacc[2][8][4];
#pragma unroll
        for (int G = 0; G < 2; G++)
#pragma unroll
            for (int nb = 0; nb < 8; nb++)
#pragma unroll
                for (int t = 0; t < 4; t++) sacc[G][nb][t] = 0.0f;
#pragma unroll
        for (int nb = 0; nb < 8; nb++) {
#pragma unroll
            for (int kc = 0; kc < 4; kc++) {
                uint32_t b0 = Kb[(nb * 8 + g) * (FLD / 2) + kc * 8 + q];
                uint32_t b1 = Kb[(nb * 8 + g) * (FLD / 2) + kc * 8 + q + 4];
                mma_f16(sacc[0][nb], qa[0][kc], b0, b1);
                mma_f16(sacc[1][nb], qa[1][kc], b0, b1);
            }
        }

        // ---- softmax per row-group (f16x2 exp2) ----
        uint32_t pa[2][4][4];
#pragma unroll
        for (int G = 0; G < 2; G++) {
            float mx0 = -CUDART_INF_F, mx1 = -CUDART_INF_F;
#pragma unroll
            for (int nb = 0; nb < 8; nb++) {
                mx0 = fmaxf(mx0, fmaxf(sacc[G][nb][0], sacc[G][nb][1]));
                mx1 = fmaxf(mx1, fmaxf(sacc[G][nb][2], sacc[G][nb][3]));
            }
            mx0 = fmaxf(mx0, __shfl_xor_sync(0xffffffffu, mx0, 1));
            mx0 = fmaxf(mx0, __shfl_xor_sync(0xffffffffu, mx0, 2));
            mx1 = fmaxf(mx1, __shfl_xor_sync(0xffffffffu, mx1, 1));
            mx1 = fmaxf(mx1, __shfl_xor_sync(0xffffffffu, mx1, 2));

            float mn0 = fmaxf(m0r[G], mx0), mn1 = fmaxf(m1r[G], mx1);
            float al0 = exp2f(m0r[G] - mn0), al1 = exp2f(m1r[G] - mn1);
            m0r[G] = mn0; m1r[G] = mn1;

            __half2 hs0 = __float2half2_rn(0.0f), hs1 = __float2half2_rn(0.0f);
#pragma unroll
            for (int kc = 0; kc < 4; kc++) {
                pa[G][kc][0] = h2exp2(pack_f16x2(sacc[G][2 * kc][1] - mn0,     sacc[G][2 * kc][0] - mn0));
                pa[G][kc][1] = h2exp2(pack_f16x2(sacc[G][2 * kc][3] - mn1,     sacc[G][2 * kc][2] - mn1));
                pa[G][kc][2] = h2exp2(pack_f16x2(sacc[G][2 * kc + 1][1] - mn0, sacc[G][2 * kc + 1][0] - mn0));
                pa[G][kc][3] = h2exp2(pack_f16x2(sacc[G][2 * kc + 1][3] - mn1, sacc[G][2 * kc + 1][2] - mn1));
                hs0 = __hadd2(hs0, __hadd2(*(__half2*)&pa[G][kc][0], *(__half2*)&pa[G][kc][2]));
                hs1 = __hadd2(hs1, __hadd2(*(__half2*)&pa[G][kc][1], *(__half2*)&pa[G][kc][3]));
            }
            float2 f0 = __half22float2(hs0), f1 = __half22float2(hs1);
            float s0 = f0.x + f0.y, s1 = f1.x + f1.y;
            s0 += __shfl_xor_sync(0xffffffffu, s0, 1);
            s0 += __shfl_xor_sync(0xffffffffu, s0, 2);
            s1 += __shfl_xor_sync(0xffffffffu, s1, 1);
            s1 += __shfl_xor_sync(0xffffffffu, s1, 2);
            l0r[G] = l0r[G] * al0 + s0;
            l1r[G] = l1r[G] * al1 + s1;

#pragma unroll
            for (int nb = 0; nb < 8; nb++) {
                oacc[G][nb][0] *= al0; oacc[G][nb][1] *= al0;
                oacc[G][nb][2] *= al1; oacc[G][nb][3] *= al1;
            }
        }

        // ---- O += P @ Vt : both row-groups share each V fragment load ----
#pragma unroll
        for (int kc = 0; kc < 4; kc++) {
#pragma unroll
            for (int nb = 0; nb < 8; nb++) {
                uint32_t vb0 = Vb[(nb * 8 + g) * (FLD / 2) + kc * 8 + q];
                uint32_t vb1 = Vb[(nb * 8 + g) * (FLD / 2) + kc * 8 + q + 4];
                mma_f16(oacc[0][nb], pa[0][kc], vb0, vb1);
                mma_f16(oacc[1][nb], pa[1][kc], vb0, vb1);
            }
        }

        buf = (buf + 1 >= 3) ? 0 : buf + 1;
    }
#undef FL_PREFETCH

    // ---- normalize + write merged [b, q, h*64+d] as fp16 ----
#pragma unroll
    for (int G = 0; G < 2; G++) {
        float inv0 = 1.0f / l0r[G], inv1 = 1.0f / l1r[G];
        int r0 = q0 + wid * 32 + G * 16 + g;
        uint32_t* og0 = (uint32_t*)(g_attn + ((size_t)(b * SQ + r0) * DMODEL) + h * DHEAD);
        uint32_t* og1 = (uint32_t*)(g_attn + ((size_t)(b * SQ + r0 + 8) * DMODEL) + h * DHEAD);
#pragma unroll
        for (int nb = 0; nb < 8; nb++) {
            og0[nb * 4 + q] = pack_f16x2(oacc[G][nb][1] * inv0, oacc[G][nb][0] * inv0);
            og1[nb * 4 + q] = pack_f16x2(oacc[G][nb][3] * inv1, oacc[G][nb][2] * inv1);
        }
    }
}

// ---------------------------------------------------------------------------
// Launch
// ---------------------------------------------------------------------------
extern "C" void kernel_launch(void* const* d_in, const int* in_sizes, int n_in,
                              void* d_out, int out_size)
{
    const float* q  = (const float*)d_in[0];
    const float* k  = (const float*)d_in[1];
    const float* v  = (const float*)d_in[2];
    const float* Wq = (const float*)d_in[3];
    const float* bq = (const float*)d_in[4];
    const float* Wk = (const float*)d_in[5];
    const float* bk = (const float*)d_in[6];
    const float* Wv = (const float*)d_in[7];
    const float* bv = (const float*)d_in[8];
    const float* Wo = (const float*)d_in[9];
    const float* bo = (const float*)d_in[10];
    float* out = (float*)d_out;

    static bool attr_done = false;
    if (!attr_done) {
        cudaFuncSetAttribute(gemm_f16_kernel<0>, cudaFuncAttributeMaxDynamicSharedMemorySize, GEMM_SMEM);
        cudaFuncSetAttribute(gemm_f16_kernel<1>, cudaFuncAttributeMaxDynamicSharedMemorySize, GEMM_SMEM);
        cudaFuncSetAttribute(flash_attn_kernel, cudaFuncAttributeMaxDynamicSharedMemorySize, FLASH_SMEM);
        attr_done = true;
    }

    // 1. Convert inputs + weights to fp16
    {
        preconvert_kernel<<<16384, 256>>>((const float4*)q, (const float4*)k, (const float4*)v,
                                          (const float4*)Wq, (const float4*)Wk,
                                          (const float4*)Wv, (const float4*)Wo);
    }

    // 2. Batched Q/K/V projections -> head-major fp16 scratch (V transposed)
    {
        dim3 ggrid(DMODEL / 128, MROWS / 128, 3);   // (8, 32, 3)
        gemm_f16_kernel<0><<<ggrid, 256, GEMM_SMEM>>>(bq, bk, bv, nullptr);
    }

    // 3. Flash attention (256 q-rows per CTA, 32 per warp)
    {
        dim3 fgrid(SQ / 256, NHEADS, NBATCH);       // (8, 16, 2)
        flash_attn_kernel<<<fgrid, 256, FLASH_SMEM>>>();
    }

    // 4. Output projection
    {
        dim3 ggrid(DMODEL / 128, MROWS / 128, 1);   // (8, 32)
        gemm_f16_kernel<1><<<ggrid, 256, GEMM_SMEM>>>(bo, nullptr, nullptr, out);
    }
}